// round 2
// baseline (speedup 1.0000x reference)
#include <cuda_runtime.h>
#include <math.h>

#define BROWS 16
#define NSAMP 524288
#define NG (NSAMP / 4)      // 131072 float4 groups per row
#define DEPTH 16            // prefetch ring depth (groups = 64 samples ahead)

// scratch (allocation-free rule: __device__ globals)
__device__ float g_v[BROWS * NSAMP];  // q * x_L, tiled: float4 index = n4*16 + b
__device__ float g_w[BROWS * NSAMP];  // w = u + v_next (y_L = q*w), same tiling

__device__ __forceinline__ float sanitize(float v) {
    if (isnan(v)) v = 0.0f;
    if (v == 0.0f) v = 1e-10f;
    return v;
}

struct RowP {
    float aA, aR, q, thr, ratio, invr, knee, gmk;
};

__device__ __forceinline__ RowP row_params(const float* __restrict__ p, int b) {
    float p0 = sanitize(p[b * 6 + 0]);
    float p1 = sanitize(p[b * 6 + 1]);
    float p2 = sanitize(p[b * 6 + 2]);
    float p3 = sanitize(p[b * 6 + 3]);
    float p4 = sanitize(p[b * 6 + 4]);
    float p5 = sanitize(p[b * 6 + 5]);
    RowP r;
    r.thr = -p0 * 60.0f;
    r.ratio = p1 * 10.0f;
    r.invr = 1.0f / r.ratio;
    float attack  = fmaxf(p2 / 10.0f, 1e-4f);
    float release = fmaxf(p3 * 3.0f, 0.005f);
    const float L9 = 2.1972245773362196f;
    r.aA = expf(-L9 / (44100.0f * attack));
    r.aR = expf(-L9 / (44100.0f * release));
    r.q = (r.aA <= r.aR) ? 1.0f : -1.0f;
    r.knee = p4 * 24.0f;
    float mk = p5 * 20.0f;
    r.gmk = exp10f(mk / 20.0f);
    return r;
}

// static gain curve -> x_L (gain reduction target, dB), exactly as reference
__device__ __forceinline__ float xl_of(float xi, const RowP& r) {
    float ax = fabsf(xi) + 1e-8f;
    float xg = 20.0f * log10f(ax);
    xg = fmaxf(xg, -96.0f);
    float d = xg - r.thr;
    float td = 2.0f * d;
    float xl;
    if (td < -r.knee) {
        xl = 0.0f;                          // y_G = x_G
    } else if (td > r.knee) {
        xl = d - d / r.ratio;               // y_G = thr + d/ratio
    } else {
        float h = (d + r.knee) * 0.5f;
        xl = -(r.invr * h * h) / (2.0f * r.knee);  // y_knee = x_G + invr*h^2/(2k)
    }
    return xl;
}

// ---------------- Kernel A: parallel x_L -> v = q*x_L (tiled transpose) -----
__global__ void k_xl(const float* __restrict__ x, const float* __restrict__ p) {
    int tid = blockIdx.x * blockDim.x + threadIdx.x;
    if (tid >= BROWS * NG) return;
    int b = tid / NG;
    int n4 = tid % NG;
    RowP r = row_params(p, b);
    float4 xv = reinterpret_cast<const float4*>(x)[b * NG + n4];
    float4 v;
    v.x = r.q * xl_of(xv.x, r);
    v.y = r.q * xl_of(xv.y, r);
    v.z = r.q * xl_of(xv.z, r);
    v.w = r.q * xl_of(xv.w, r);
    reinterpret_cast<float4*>(g_v)[n4 * BROWS + b] = v;
}

// ---------------- Kernel B: serial scan, 1 warp, 16 lanes -------------------
#define STEP(C)                                                        \
    do {                                                               \
        float c_ = (C);                                                \
        u = fmaxf(fmaf(aA, u, c_), fmaf(aR, u, c_));                   \
    } while (0)

__global__ void k_scan(const float* __restrict__ p) {
    int b = threadIdx.x;  // 0..15, one lane per row
    RowP r = row_params(p, b);
    float aA = r.aA, aR = r.aR;

    const float4* V = reinterpret_cast<const float4*>(g_v);
    float4* W = reinterpret_cast<float4*>(g_w);

    float4 ring[DEPTH];
#pragma unroll
    for (int i = 0; i < DEPTH; ++i) ring[i] = V[i * BROWS + b];

    float4 cur = ring[0];
    float u = -cur.y;  // u_0 = q*(y_0 - xl_1) = -v[1]

    // group 0: n = 0 (y_L=0 placeholder), steps n = 1,2,3
    {
        float4 nxt = ring[1];
        float4 w;
        w.x = 0.0f;
        STEP(cur.y - cur.z); w.y = u + cur.z;
        STEP(cur.z - cur.w); w.z = u + cur.w;
        STEP(cur.w - nxt.x); w.w = u + nxt.x;
        W[b] = w;
        ring[0] = V[DEPTH * BROWS + b];  // prefetch group 16 -> slot 0
        cur = nxt;
    }

    int gb = 1;
    // main loop: unrolled by DEPTH so ring indices are compile-time (regs)
    for (; gb + DEPTH <= NG - 1; gb += DEPTH) {
#pragma unroll
        for (int j = 0; j < DEPTH; ++j) {
            int g = gb + j;                     // gb ≡ 1 (mod 16)
            float4 nxt = ring[(j + 2) & (DEPTH - 1)];   // group g+1
            int pg = g + DEPTH;
            pg = (pg < NG) ? pg : (NG - 1);
            ring[(j + 1) & (DEPTH - 1)] = V[pg * BROWS + b];  // prefetch g+16
            float4 w;
            STEP(cur.x - cur.y); w.x = u + cur.y;
            STEP(cur.y - cur.z); w.y = u + cur.z;
            STEP(cur.z - cur.w); w.z = u + cur.w;
            STEP(cur.w - nxt.x); w.w = u + nxt.x;
            W[g * BROWS + b] = w;
            cur = nxt;
        }
    }

    // tail groups with direct loads (latency-exposed but only <=15 groups)
    for (int g = gb; g <= NG - 2; ++g) {
        float4 nxt = V[(g + 1) * BROWS + b];
        float4 w;
        STEP(cur.x - cur.y); w.x = u + cur.y;
        STEP(cur.y - cur.z); w.y = u + cur.z;
        STEP(cur.z - cur.w); w.z = u + cur.w;
        STEP(cur.w - nxt.x); w.w = u + nxt.x;
        W[g * BROWS + b] = w;
        cur = nxt;
    }

    // last group: v_N treated as 0 (w_{N-1} = u_{N-1})
    {
        float4 w;
        STEP(cur.x - cur.y); w.x = u + cur.y;
        STEP(cur.y - cur.z); w.y = u + cur.z;
        STEP(cur.z - cur.w); w.z = u + cur.w;
        STEP(cur.w);         w.w = u;
        W[(NG - 1) * BROWS + b] = w;
    }
}

// ---------------- Kernel C: parallel output --------------------------------
__device__ __forceinline__ float drc_out(float xi, float wi, const RowP& r) {
    float y = fmaxf(r.q * wi, -96.0f);                 // clip(y_L, -96)
    float val = xi * exp10f(-y / 20.0f) * r.gmk;
    return isfinite(val) ? val : 0.0f;
}

__global__ void k_out(const float* __restrict__ x, const float* __restrict__ p,
                      float* __restrict__ out) {
    int tid = blockIdx.x * blockDim.x + threadIdx.x;
    if (tid >= BROWS * NG) return;
    int b = tid / NG;
    int n4 = tid % NG;
    RowP r = row_params(p, b);
    float4 w = reinterpret_cast<const float4*>(g_w)[n4 * BROWS + b];
    float4 xv = reinterpret_cast<const float4*>(x)[b * NG + n4];
    float4 o;
    o.x = drc_out(xv.x, w.x, r);
    o.y = drc_out(xv.y, w.y, r);
    o.z = drc_out(xv.z, w.z, r);
    o.w = drc_out(xv.w, w.w, r);
    reinterpret_cast<float4*>(out)[b * NG + n4] = o;
}

extern "C" void kernel_launch(void* const* d_in, const int* in_sizes, int n_in,
                              void* d_out, int out_size) {
    const float* x = (const float*)d_in[0];      // [16, 524288] f32
    const float* p = (const float*)d_in[1];      // [16, 6] f32
    float* out = (float*)d_out;                  // [16, 524288] f32

    int total = BROWS * NG;
    int threads = 256;
    int blocks = (total + threads - 1) / threads;

    k_xl<<<blocks, threads>>>(x, p);
    k_scan<<<1, 16>>>(p);
    k_out<<<blocks, threads>>>(x, p, out);
}

// round 3
// speedup vs baseline: 3.0922x; 3.0922x over previous
#include <cuda_runtime.h>
#include <math.h>

#define BROWS 16
#define NSAMP 524288
#define NP    (NSAMP + 16)      // padded row stride (padding stays zero-init)
#define LSEG  128
#define SSEG  4096              // segments per row
#define NMAPS (SSEG - 1)        // maps needed per row
#define TSTR  136               // floats per map: [0]=t0, [8..135]=t1..t128
#define PF    8                 // k_bound prefetch depth

__device__ float g_v[BROWS * NP];                    // q * x_L, row-major padded
__device__ float g_t[(size_t)BROWS * SSEG * TSTR];   // per-segment map intercepts
__device__ float g_U[BROWS * SSEG];                  // exact segment seed states

__device__ __forceinline__ float sanitize(float v) {
    if (isnan(v)) v = 0.0f;
    if (v == 0.0f) v = 1e-10f;
    return v;
}

struct RowP { float aA, aR, q, thr, ratio, invr, knee, gmk; };

__device__ __forceinline__ RowP row_params(const float* __restrict__ p, int b) {
    float p0 = sanitize(p[b * 6 + 0]);
    float p1 = sanitize(p[b * 6 + 1]);
    float p2 = sanitize(p[b * 6 + 2]);
    float p3 = sanitize(p[b * 6 + 3]);
    float p4 = sanitize(p[b * 6 + 4]);
    float p5 = sanitize(p[b * 6 + 5]);
    RowP r;
    r.thr = -p0 * 60.0f;
    r.ratio = p1 * 10.0f;
    r.invr = 1.0f / r.ratio;
    float attack  = fmaxf(p2 / 10.0f, 1e-4f);
    float release = fmaxf(p3 * 3.0f, 0.005f);
    const float L9 = 2.1972245773362196f;
    r.aA = expf(-L9 / (44100.0f * attack));
    r.aR = expf(-L9 / (44100.0f * release));
    r.q = (r.aA <= r.aR) ? 1.0f : -1.0f;
    r.knee = p4 * 24.0f;
    float mk = p5 * 20.0f;
    r.gmk = exp10f(mk / 20.0f);
    return r;
}

__device__ __forceinline__ float xl_of(float xi, const RowP& r) {
    float ax = fabsf(xi) + 1e-8f;
    float xg = 20.0f * log10f(ax);
    xg = fmaxf(xg, -96.0f);
    float d = xg - r.thr;
    float td = 2.0f * d;
    float xl;
    if (td < -r.knee) {
        xl = 0.0f;
    } else if (td > r.knee) {
        xl = d - d / r.ratio;
    } else {
        float h = (d + r.knee) * 0.5f;
        xl = -(r.invr * h * h) / (2.0f * r.knee);
    }
    return xl;
}

// ---------------- Kernel 1: v = q * x_L, row-major padded ------------------
__global__ void k_xl(const float* __restrict__ x, const float* __restrict__ p) {
    int tid = blockIdx.x * blockDim.x + threadIdx.x;
    const int NG = NSAMP / 4;
    if (tid >= BROWS * NG) return;
    int b = tid / NG;
    int n4 = tid % NG;
    RowP r = row_params(p, b);
    float4 xv = reinterpret_cast<const float4*>(x)[(size_t)b * NG + n4];
    float4 v;
    v.x = r.q * xl_of(xv.x, r);
    v.y = r.q * xl_of(xv.y, r);
    v.z = r.q * xl_of(xv.z, r);
    v.w = r.q * xl_of(xv.w, r);
    reinterpret_cast<float4*>(g_v)[(size_t)b * (NP / 4) + n4] = v;
}

// ---------------- Kernel 2: per-segment max-affine map (warp/segment) ------
// Map of segment s: u_{128(s+1)} = max_{j=0..128}( sig_j * u_{128 s} + t_j ),
// wavefront: t'_j = c + max(aA t_j, aR t_{j-1});  t'_0 = c + aA t_0.
__global__ void k_map(const float* __restrict__ p) {
    __shared__ float vbuf[8][TSTR];
    __shared__ float csm[8][LSEG];
    int wid  = threadIdx.x >> 5;
    int lane = threadIdx.x & 31;
    int w = blockIdx.x * 8 + wid;          // 0 .. 16*4095-1
    int b = w / NMAPS;
    int s = w - b * NMAPS;
    RowP rp = row_params(p, b);
    float aA = rp.aA, aR = rp.aR;

    const float* vrow = g_v + (size_t)b * NP + s * LSEG;
    for (int i = lane; i < TSTR; i += 32) vbuf[wid][i] = vrow[i];
    __syncwarp();
    for (int i = lane; i < LSEG; i += 32)
        csm[wid][i] = vbuf[wid][i + 1] - vbuf[wid][i + 2];
    __syncwarp();

    const float NI = __int_as_float(0xff800000);   // -inf sentinel
    float t0 = 0.0f;                                // line j=0 (identity start)
    float r0 = NI, r1 = NI, r2 = NI, r3 = NI;       // lines 4*lane+1 .. 4*lane+4

#pragma unroll 4
    for (int i = 0; i < LSEG; ++i) {
        float c = csm[wid][i];
        float nb = __shfl_up_sync(0xffffffffu, r3, 1);
        if (lane == 0) nb = t0;
        r3 = fmaxf(fmaf(aA, r3, c), fmaf(aR, r2, c));
        r2 = fmaxf(fmaf(aA, r2, c), fmaf(aR, r1, c));
        r1 = fmaxf(fmaf(aA, r1, c), fmaf(aR, r0, c));
        r0 = fmaxf(fmaf(aA, r0, c), fmaf(aR, nb, c));
        t0 = fmaf(aA, t0, c);
    }

    float* T = g_t + ((size_t)b * SSEG + s) * TSTR;
    if (lane == 0) T[0] = t0;
    reinterpret_cast<float4*>(T + 8)[lane] = make_float4(r0, r1, r2, r3);
}

// ---------------- Kernel 3: chain segment boundaries (warp/row) ------------
__global__ void k_bound(const float* __restrict__ p) {
    int b = blockIdx.x;
    int lane = threadIdx.x;
    RowP rp = row_params(p, b);
    float la = log2f(rp.aA), lr = log2f(rp.aR);
    float sig[4];
#pragma unroll
    for (int i = 0; i < 4; i++) {
        float j = (float)(4 * lane + 1 + i);
        sig[i] = exp2f(la * ((float)LSEG - j) + lr * j);
    }
    float sig0 = (lane == 0) ? exp2f(la * (float)LSEG) : 0.0f;
    const float NI = __int_as_float(0xff800000);

    float u = -g_v[(size_t)b * NP + 1];          // u_0 = -v[1]
    if (lane == 0) g_U[b * SSEG + 0] = u;

    const float* Tb = g_t + (size_t)b * SSEG * TSTR;
    float4 ta[PF];
    float t0a[PF];
#pragma unroll
    for (int k = 0; k < PF; k++) {
        const float* ts = Tb + (size_t)k * TSTR;
        ta[k]  = reinterpret_cast<const float4*>(ts + 8)[lane];
        t0a[k] = ts[0];
    }

    for (int s = 0; s < NMAPS; ++s) {
        int slot = s & (PF - 1);
        float4 A = ta[slot];
        float t0v = (lane == 0) ? t0a[slot] : NI;
        int sp = s + PF;
        if (sp < NMAPS) {
            const float* ts = Tb + (size_t)sp * TSTR;
            ta[slot]  = reinterpret_cast<const float4*>(ts + 8)[lane];
            t0a[slot] = ts[0];
        }
        float m0 = fmaf(sig[0], u, A.x);
        float m1 = fmaf(sig[1], u, A.y);
        float m2 = fmaf(sig[2], u, A.z);
        float m3 = fmaf(sig[3], u, A.w);
        float m4 = fmaf(sig0, u, t0v);           // lanes!=0: fma(0,u,-inf) = -inf
        float m = fmaxf(fmaxf(fmaxf(m0, m1), fmaxf(m2, m3)), m4);
        // monotone float->u32 map, warp allreduce max (REDUX.UMAX), map back
        unsigned bm = __float_as_uint(m);
        unsigned mm = bm ^ (((unsigned)((int)bm >> 31)) | 0x80000000u);
        unsigned rm = __reduce_max_sync(0xffffffffu, mm);
        u = __uint_as_float((rm & 0x80000000u) ? (rm ^ 0x80000000u) : ~rm);
        if (lane == 0) g_U[b * SSEG + s + 1] = u;
    }
}

// ---------------- Kernel 4: per-segment rerun + fused output ---------------
#define STEPF(C) do { float c_ = (C); u = fmaxf(fmaf(aA, u, c_), fmaf(aR, u, c_)); } while (0)

__device__ __forceinline__ float emitv(float xi, float w, float q, float gmk) {
    float y = fmaxf(q * w, -96.0f);
    float val = xi * exp10f(-y / 20.0f) * gmk;
    return isfinite(val) ? val : 0.0f;
}

__global__ void k_apply(const float* __restrict__ x, const float* __restrict__ p,
                        float* __restrict__ out) {
    int tid = blockIdx.x * blockDim.x + threadIdx.x;   // 65536 threads
    int b = tid >> 12;
    int s = tid & (SSEG - 1);
    RowP r = row_params(p, b);
    float aA = r.aA, aR = r.aR, q = r.q, gmk = r.gmk;
    float u = g_U[(b << 12) + s];

    const float4* V4 = reinterpret_cast<const float4*>(g_v) + (size_t)b * (NP / 4) + s * (LSEG / 4);
    const float4* X4 = reinterpret_cast<const float4*>(x) + (size_t)b * (NSAMP / 4) + s * (LSEG / 4);
    float4* O4 = reinterpret_cast<float4*>(out) + (size_t)b * (NSAMP / 4) + s * (LSEG / 4);

    float4 cur = V4[0];
#pragma unroll 4
    for (int g = 0; g < LSEG / 4; ++g) {
        float4 nxt = V4[g + 1];          // last read hits zero padding (v_N = 0)
        float4 xv = X4[g];
        float4 o;
        o.x = emitv(xv.x, u + cur.y, q, gmk); STEPF(cur.y - cur.z);
        o.y = emitv(xv.y, u + cur.z, q, gmk); STEPF(cur.z - cur.w);
        o.z = emitv(xv.z, u + cur.w, q, gmk); STEPF(cur.w - nxt.x);
        o.w = emitv(xv.w, u + nxt.x, q, gmk); STEPF(nxt.x - nxt.y);
        O4[g] = o;
        cur = nxt;
    }
}

extern "C" void kernel_launch(void* const* d_in, const int* in_sizes, int n_in,
                              void* d_out, int out_size) {
    const float* x = (const float*)d_in[0];      // [16, 524288] f32
    const float* p = (const float*)d_in[1];      // [16, 6] f32
    float* out = (float*)d_out;

    int total = BROWS * (NSAMP / 4);
    k_xl<<<(total + 255) / 256, 256>>>(x, p);
    k_map<<<(BROWS * NMAPS) / 8, 256>>>(p);      // 8190 blocks, 8 warps each
    k_bound<<<BROWS, 32>>>(p);
    k_apply<<<(BROWS * SSEG) / 256, 256>>>(x, p, out);
}

// round 4
// speedup vs baseline: 7.7847x; 2.5176x over previous
#include <cuda_runtime.h>
#include <math.h>

#define BROWS 16
#define NSAMP 524288
#define NP    (NSAMP + 16)      // padded row stride (padding stays zero-init)
#define LSEG  128
#define SSEG  4096              // segments per row
#define NMAPS (SSEG - 1)        // maps needed per row
#define TSTR  160               // floats per map: [0]=t0, [32..159]=t1..t128 (640B, 128B-aligned)
#define PF    8                 // k_bound prefetch depth (compile-time slots)

__device__ float g_v[BROWS * NP];                    // q * x_L, row-major padded
__device__ float g_t[(size_t)BROWS * SSEG * TSTR];   // per-segment map intercepts
__device__ float g_U[BROWS * SSEG];                  // exact segment seed states

__device__ __forceinline__ float sanitize(float v) {
    if (isnan(v)) v = 0.0f;
    if (v == 0.0f) v = 1e-10f;
    return v;
}

struct RowP { float aA, aR, q, thr, ratio, invr, knee, gmk; };

__device__ __forceinline__ RowP row_params(const float* __restrict__ p, int b) {
    float p0 = sanitize(p[b * 6 + 0]);
    float p1 = sanitize(p[b * 6 + 1]);
    float p2 = sanitize(p[b * 6 + 2]);
    float p3 = sanitize(p[b * 6 + 3]);
    float p4 = sanitize(p[b * 6 + 4]);
    float p5 = sanitize(p[b * 6 + 5]);
    RowP r;
    r.thr = -p0 * 60.0f;
    r.ratio = p1 * 10.0f;
    r.invr = 1.0f / r.ratio;
    float attack  = fmaxf(p2 / 10.0f, 1e-4f);
    float release = fmaxf(p3 * 3.0f, 0.005f);
    const float L9 = 2.1972245773362196f;
    r.aA = expf(-L9 / (44100.0f * attack));
    r.aR = expf(-L9 / (44100.0f * release));
    r.q = (r.aA <= r.aR) ? 1.0f : -1.0f;
    r.knee = p4 * 24.0f;
    float mk = p5 * 20.0f;
    r.gmk = exp10f(mk / 20.0f);
    return r;
}

__device__ __forceinline__ float xl_of(float xi, const RowP& r) {
    float ax = fabsf(xi) + 1e-8f;
    float xg = 20.0f * log10f(ax);
    xg = fmaxf(xg, -96.0f);
    float d = xg - r.thr;
    float td = 2.0f * d;
    float xl;
    if (td < -r.knee) {
        xl = 0.0f;
    } else if (td > r.knee) {
        xl = d - d / r.ratio;
    } else {
        float h = (d + r.knee) * 0.5f;
        xl = -(r.invr * h * h) / (2.0f * r.knee);
    }
    return xl;
}

// ---------------- Kernel 1: v = q * x_L, row-major padded ------------------
__global__ void k_xl(const float* __restrict__ x, const float* __restrict__ p) {
    int tid = blockIdx.x * blockDim.x + threadIdx.x;
    const int NG = NSAMP / 4;
    if (tid >= BROWS * NG) return;
    int b = tid / NG;
    int n4 = tid % NG;
    RowP r = row_params(p, b);
    float4 xv = reinterpret_cast<const float4*>(x)[(size_t)b * NG + n4];
    float4 v;
    v.x = r.q * xl_of(xv.x, r);
    v.y = r.q * xl_of(xv.y, r);
    v.z = r.q * xl_of(xv.z, r);
    v.w = r.q * xl_of(xv.w, r);
    reinterpret_cast<float4*>(g_v)[(size_t)b * (NP / 4) + n4] = v;
}

// ---------------- Kernel 2: per-segment max-affine map (warp/segment) ------
// Map of segment s: u_{128(s+1)} = max_{j=0..128}( sig_j * u_{128 s} + t_j ),
// wavefront: t'_j = c + max(aA t_j, aR t_{j-1});  t'_0 = c + aA t_0.
__global__ void k_map(const float* __restrict__ p) {
    __shared__ float csm[8][LSEG + 2];
    int wid  = threadIdx.x >> 5;
    int lane = threadIdx.x & 31;
    int w = blockIdx.x * 8 + wid;          // 0 .. 16*4095-1
    int b = w / NMAPS;
    int s = w - b * NMAPS;
    RowP rp = row_params(p, b);
    float aA = rp.aA, aR = rp.aR;

    const float* vrow = g_v + (size_t)b * NP + s * LSEG;
    // c_i = v[sL+1+i] - v[sL+2+i], i = 0..127
    for (int i = lane; i < LSEG; i += 32)
        csm[wid][i] = vrow[i + 1] - vrow[i + 2];
    __syncwarp();

    const float NI = __int_as_float(0xff800000);   // -inf sentinel
    float t0 = 0.0f;                                // line j=0 (identity start)
    float r0 = NI, r1 = NI, r2 = NI, r3 = NI;       // lines 4*lane+1 .. 4*lane+4

#pragma unroll 4
    for (int i = 0; i < LSEG; ++i) {
        float c = csm[wid][i];
        float nb = __shfl_up_sync(0xffffffffu, r3, 1);
        if (lane == 0) nb = t0;
        r3 = fmaxf(fmaf(aA, r3, c), fmaf(aR, r2, c));
        r2 = fmaxf(fmaf(aA, r2, c), fmaf(aR, r1, c));
        r1 = fmaxf(fmaf(aA, r1, c), fmaf(aR, r0, c));
        r0 = fmaxf(fmaf(aA, r0, c), fmaf(aR, nb, c));
        t0 = fmaf(aA, t0, c);
    }

    float* T = g_t + ((size_t)b * SSEG + s) * TSTR;
    if (lane == 0) T[0] = t0;
    reinterpret_cast<float4*>(T + 32)[lane] = make_float4(r0, r1, r2, r3);
}

// ---------------- Kernel 3: chain segment boundaries (warp/row) ------------
__global__ void k_bound(const float* __restrict__ p) {
    int b = blockIdx.x;
    int lane = threadIdx.x;
    RowP rp = row_params(p, b);
    float la = log2f(rp.aA), lr = log2f(rp.aR);
    float sig[4];
#pragma unroll
    for (int i = 0; i < 4; i++) {
        float j = (float)(4 * lane + 1 + i);
        sig[i] = exp2f(la * ((float)LSEG - j) + lr * j);
    }
    float sig0 = (lane == 0) ? exp2f(la * (float)LSEG) : 0.0f;
    const float NI = __int_as_float(0xff800000);

    float u = -g_v[(size_t)b * NP + 1];          // u_0 = -v[1]
    if (lane == 0) g_U[b * SSEG + 0] = u;

    const float* Tb = g_t + (size_t)b * SSEG * TSTR;
    float4 ta[PF];
    float t0a[PF];
#pragma unroll
    for (int k = 0; k < PF; k++) {
        const float* ts = Tb + (size_t)k * TSTR;
        ta[k]  = reinterpret_cast<const float4*>(ts + 32)[lane];
        t0a[k] = ts[0];
    }

    // SSEG iterations total; last one (s = NMAPS) computes a discarded value.
    for (int sb = 0; sb < SSEG; sb += PF) {
#pragma unroll
        for (int j = 0; j < PF; ++j) {           // compile-time slot -> regs
            int s = sb + j;
            float4 A = ta[j];
            float t0v = (lane == 0) ? t0a[j] : NI;
            int sp = s + PF;
            if (sp < SSEG) {
                const float* ts = Tb + (size_t)sp * TSTR;
                ta[j]  = reinterpret_cast<const float4*>(ts + 32)[lane];
                t0a[j] = ts[0];
            }
            float m0 = fmaf(sig[0], u, A.x);
            float m1 = fmaf(sig[1], u, A.y);
            float m2 = fmaf(sig[2], u, A.z);
            float m3 = fmaf(sig[3], u, A.w);
            float m4 = fmaf(sig0, u, t0v);       // lanes!=0: fma(0,u,-inf) = -inf
            float m = fmaxf(fmaxf(fmaxf(m0, m1), fmaxf(m2, m3)), m4);
            // monotone float->u32 map, warp allreduce max (REDUX.UMAX), map back
            unsigned bm = __float_as_uint(m);
            unsigned mm = bm ^ (((unsigned)((int)bm >> 31)) | 0x80000000u);
            unsigned rm = __reduce_max_sync(0xffffffffu, mm);
            u = __uint_as_float((rm & 0x80000000u) ? (rm ^ 0x80000000u) : ~rm);
            if (lane == 0 && (s + 1) < SSEG) g_U[b * SSEG + s + 1] = u;
        }
    }
}

// ---------------- Kernel 4: per-segment rerun + fused output ---------------
#define STEPF(C) do { float c_ = (C); u = fmaxf(fmaf(aA, u, c_), fmaf(aR, u, c_)); } while (0)

__device__ __forceinline__ float emitv(float xi, float w, float q, float gmk) {
    float y = fmaxf(q * w, -96.0f);
    float val = xi * exp10f(-y / 20.0f) * gmk;
    return isfinite(val) ? val : 0.0f;
}

__global__ void k_apply(const float* __restrict__ x, const float* __restrict__ p,
                        float* __restrict__ out) {
    int tid = blockIdx.x * blockDim.x + threadIdx.x;   // 65536 threads
    int b = tid >> 12;
    int s = tid & (SSEG - 1);
    RowP r = row_params(p, b);
    float aA = r.aA, aR = r.aR, q = r.q, gmk = r.gmk;
    float u = g_U[(b << 12) + s];

    const float4* V4 = reinterpret_cast<const float4*>(g_v) + (size_t)b * (NP / 4) + s * (LSEG / 4);
    const float4* X4 = reinterpret_cast<const float4*>(x) + (size_t)b * (NSAMP / 4) + s * (LSEG / 4);
    float4* O4 = reinterpret_cast<float4*>(out) + (size_t)b * (NSAMP / 4) + s * (LSEG / 4);

    float4 cur = V4[0];
#pragma unroll 4
    for (int g = 0; g < LSEG / 4; ++g) {
        float4 nxt = V4[g + 1];          // last read hits zero padding (v_N = 0)
        float4 xv = X4[g];
        float4 o;
        o.x = emitv(xv.x, u + cur.y, q, gmk); STEPF(cur.y - cur.z);
        o.y = emitv(xv.y, u + cur.z, q, gmk); STEPF(cur.z - cur.w);
        o.z = emitv(xv.z, u + cur.w, q, gmk); STEPF(cur.w - nxt.x);
        o.w = emitv(xv.w, u + nxt.x, q, gmk); STEPF(nxt.x - nxt.y);
        O4[g] = o;
        cur = nxt;
    }
}

extern "C" void kernel_launch(void* const* d_in, const int* in_sizes, int n_in,
                              void* d_out, int out_size) {
    const float* x = (const float*)d_in[0];      // [16, 524288] f32
    const float* p = (const float*)d_in[1];      // [16, 6] f32
    float* out = (float*)d_out;

    int total = BROWS * (NSAMP / 4);
    k_xl<<<(total + 255) / 256, 256>>>(x, p);
    k_map<<<(BROWS * NMAPS + 7) / 8, 256>>>(p);  // 8190 blocks, 8 warps each
    k_bound<<<BROWS, 32>>>(p);
    k_apply<<<(BROWS * SSEG) / 256, 256>>>(x, p, out);
}